// round 11
// baseline (speedup 1.0000x reference)
#include <cuda_runtime.h>
#include <cuda_fp16.h>
#include <cstdint>

// ============================================================
// out[b,k,c] = softmax_m( tanh(e[b,m]·W1[k] + d[b,k]·W2[m]) ) · x[b,m,c]
// B=16, N=2048, D=128.
// Flash-style fused attention, mma.sync.m16n8k16 + ldmatrix + cp.async.
// tanh bounds scores in [-1,1] -> no online max rescaling needed.
// R10: software pipeline at 32-key half-chunk granularity — QK(next half)
//      interleaved with exp+PV(current half) in one barrier-free block so
//      MUFU and PV-tensor hide under QK ldsm/mma latency. S split 64->32
//      regs enables double-buffered S. f16x2 weights + ones-MMA denom (R9).
// ============================================================

#define DEVI __device__ __forceinline__

constexpr int B_ = 16, N_ = 2048, D_ = 128, F_ = 256;
constexpr int MT = 256;              // queries per CTA
constexpr int KT = 64;               // keys per chunk
constexpr int NCHUNK = N_ / KT;      // 32

constexpr uint32_t ONES_H2 = 0x3C003C00u;   // half2(1.0, 1.0)

// ---------------- device scratch -------------------------------------------
__device__ __half g_Qf[(size_t)B_ * N_ * F_];   // [b,k,256] = [W1[k] | d[b,k]]
__device__ __half g_Kf[(size_t)B_ * N_ * F_];   // [b,m,256] = [e[b,m] | W2[m]]
__device__ __half g_XT[(size_t)B_ * D_ * N_];   // [b,c,m]   = x[b,m,c]

// ---------------- SMEM layout (bytes), XOR-swizzled, no padding -------------
constexpr int SM_Q   = 0;
constexpr int QSIZE  = MT * 512;                // 131072
constexpr int KSTAGE = KT * 512;                // 32768
constexpr int SM_K   = SM_Q + QSIZE;
constexpr int XSTAGE = D_ * 128;                // 16384
constexpr int SM_X   = SM_K + 2 * KSTAGE;
constexpr int SMEM_TOTAL = SM_X + 2 * XSTAGE;   // 229376 (224 KB)

// ---------------- PTX helpers ----------------------------------------------
DEVI uint32_t smem_u32(const void* p) {
    uint32_t a;
    asm("{ .reg .u64 t; cvta.to.shared.u64 t, %1; cvt.u32.u64 %0, t; }" : "=r"(a) : "l"(p));
    return a;
}

DEVI void cp_async16(uint32_t dst, const void* src) {
    asm volatile("cp.async.cg.shared.global [%0], [%1], 16;" :: "r"(dst), "l"(src) : "memory");
}
DEVI void cp_commit() { asm volatile("cp.async.commit_group;" ::: "memory"); }
DEVI void cp_wait0()  { asm volatile("cp.async.wait_group 0;" ::: "memory"); }
DEVI void cp_wait1()  { asm volatile("cp.async.wait_group 1;" ::: "memory"); }

DEVI void ldsm4(uint32_t r[4], uint32_t addr) {
    asm volatile("ldmatrix.sync.aligned.m8n8.x4.shared.b16 {%0,%1,%2,%3}, [%4];"
                 : "=r"(r[0]), "=r"(r[1]), "=r"(r[2]), "=r"(r[3]) : "r"(addr));
}
DEVI void mma16816(float d[4], const uint32_t a[4], uint32_t b0, uint32_t b1) {
    asm volatile("mma.sync.aligned.m16n8k16.row.col.f32.f16.f16.f32 "
                 "{%0,%1,%2,%3}, {%4,%5,%6,%7}, {%8,%9}, {%0,%1,%2,%3};"
                 : "+f"(d[0]), "+f"(d[1]), "+f"(d[2]), "+f"(d[3])
                 : "r"(a[0]), "r"(a[1]), "r"(a[2]), "r"(a[3]), "r"(b0), "r"(b1));
}

// pack two fp32 -> f16x2 (same operand convention as the passing R9 kernel)
DEVI uint32_t cvt_f16x2(float hi_f, float lo_f) {
    uint32_t r;
    asm("cvt.rn.f16x2.f32 %0, %1, %2;" : "=r"(r) : "f"(hi_f), "f"(lo_f));
    return r;
}
// w = exp(tanh(s)-1) elementwise on f16x2: ex2( l2e*tanh(s) - l2e )
DEVI uint32_t wfun2(uint32_t s) {
    const uint32_t C  = 0x3DC53DC5u;   // half2(+1.4427)
    const uint32_t NC = 0xBDC5BDC5u;   // half2(-1.4427)
    uint32_t t, u, w;
    asm("tanh.approx.f16x2 %0, %1;" : "=r"(t) : "r"(s));
    asm("fma.rn.f16x2 %0, %1, %2, %3;" : "=r"(u) : "r"(t), "r"(C), "r"(NC));
    asm("ex2.approx.f16x2 %0, %1;" : "=r"(w) : "r"(u));
    return w;
}

DEVI uint32_t h2_as_u32(__half2 h) { uint32_t u; __builtin_memcpy(&u, &h, 4); return u; }

// ---------------- prep: Qf/Kf fp16 feature matrices -------------------------
__global__ void build_qk(const float* __restrict__ e, const float* __restrict__ d,
                         const float* __restrict__ W1, const float* __restrict__ W2) {
    size_t idx = (size_t)blockIdx.x * blockDim.x + threadIdx.x;
    if (idx >= (size_t)B_ * N_ * (F_ / 4)) return;
    int fg = (int)(idx & 63);
    int k  = (int)((idx >> 6) & (N_ - 1));
    int b  = (int)(idx >> 17);
    int f = fg * 4;
    float4 qv, kv;
    if (f < 128) {
        qv = *(const float4*)(W1 + (size_t)k * D_ + f);
        kv = *(const float4*)(e + ((size_t)(b * N_ + k)) * D_ + f);
    } else {
        qv = *(const float4*)(d + ((size_t)(b * N_ + k)) * D_ + (f - 128));
        kv = *(const float4*)(W2 + (size_t)k * D_ + (f - 128));
    }
    __half2 q01 = __floats2half2_rn(qv.x, qv.y), q23 = __floats2half2_rn(qv.z, qv.w);
    __half2 k01 = __floats2half2_rn(kv.x, kv.y), k23 = __floats2half2_rn(kv.z, kv.w);
    *(uint2*)(g_Qf + ((size_t)(b * N_ + k)) * F_ + f) = make_uint2(h2_as_u32(q01), h2_as_u32(q23));
    *(uint2*)(g_Kf + ((size_t)(b * N_ + k)) * F_ + f) = make_uint2(h2_as_u32(k01), h2_as_u32(k23));
}

// ---------------- prep: XT[b,c,m] = fp16(x[b,m,c]) --------------------------
__global__ void transpose_x(const float* __restrict__ x) {
    __shared__ float tile[32][33];
    int b = blockIdx.z;
    int m0 = blockIdx.x * 32, c0 = blockIdx.y * 32;
    int tx = threadIdx.x, ty = threadIdx.y;
#pragma unroll
    for (int i = 0; i < 4; i++)
        tile[ty + 8 * i][tx] = x[((size_t)(b * N_ + m0 + ty + 8 * i)) * D_ + c0 + tx];
    __syncthreads();
#pragma unroll
    for (int i = 0; i < 4; i++)
        g_XT[((size_t)(b * D_ + c0 + ty + 8 * i)) * N_ + m0 + tx] =
            __float2half_rn(tile[tx][ty + 8 * i]);
}

// ---------------- chunk loader: K (64x256) + XT (128x64), swizzled ----------
DEVI void load_chunk(int b, int m0, int stage, uint32_t sb, int tid) {
    const uint32_t stK = sb + SM_K + stage * KSTAGE;
    const uint32_t stX = sb + SM_X + stage * XSTAGE;
    const __half* kbase = g_Kf + ((size_t)(b * N_ + m0)) * F_;
#pragma unroll
    for (int i = 0; i < 8; i++) {
        int lin = tid + i * 256;          // 0..2047
        int row = lin >> 5;               // 0..63
        int ch  = lin & 31;
        cp_async16(stK + row * 512 + ((ch ^ (row & 7)) << 4),
                   kbase + (size_t)row * F_ + ch * 8);
    }
    const __half* xbase = g_XT + (size_t)b * D_ * N_ + m0;
#pragma unroll
    for (int i = 0; i < 4; i++) {
        int lin = tid + i * 256;          // 0..1023
        int row = lin >> 3;               // c: 0..127
        int ch  = lin & 7;
        cp_async16(stX + row * 128 + ((ch ^ (row & 7)) << 4),
                   xbase + (size_t)row * N_ + ch * 8);
    }
    cp_commit();
}

// ---------------- compute pieces -------------------------------------------
// One kt step of QK for a 32-key half (ng in {2h, 2h+1}).
DEVI void qk_step(int kt, float S[2][4][4], uint32_t stK, int h,
                  uint32_t qrow0, uint32_t qrow1, int brow, int ahi, int bhi, int xl) {
    const uint32_t cswA = (uint32_t)(((kt * 2 + ahi) ^ xl) << 4);
    const uint32_t cswB = (uint32_t)(((kt * 2 + bhi) ^ xl) << 4);
    uint32_t qa0[4], qa1[4];
    ldsm4(qa0, qrow0 + cswA);
    ldsm4(qa1, qrow1 + cswA);
    const uint32_t krow = stK + (uint32_t)brow * 512;
#pragma unroll
    for (int g = 0; g < 2; g++) {
        const int ng = 2 * h + g;
        uint32_t kb[4];
        ldsm4(kb, krow + ng * 16 * 512 + cswB);
        mma16816(S[0][2 * g],     qa0, kb[0], kb[1]);
        mma16816(S[0][2 * g + 1], qa0, kb[2], kb[3]);
        mma16816(S[1][2 * g],     qa1, kb[0], kb[1]);
        mma16816(S[1][2 * g + 1], qa1, kb[2], kb[3]);
    }
}

// weights for one 16-key group g of a half: Pf fragments + denominator mma
DEVI void exp_piece(int g, const float S[2][4][4], uint32_t Pf[2][4], float den[2][4]) {
#pragma unroll
    for (int t = 0; t < 2; t++) {
        Pf[t][0] = wfun2(cvt_f16x2(S[t][2 * g][1],     S[t][2 * g][0]));      // row g0, k0-7
        Pf[t][1] = wfun2(cvt_f16x2(S[t][2 * g][3],     S[t][2 * g][2]));      // row g8, k0-7
        Pf[t][2] = wfun2(cvt_f16x2(S[t][2 * g + 1][1], S[t][2 * g + 1][0]));  // row g0, k8-15
        Pf[t][3] = wfun2(cvt_f16x2(S[t][2 * g + 1][3], S[t][2 * g + 1][2]));  // row g8, k8-15
        mma16816(den[t], Pf[t], ONES_H2, ONES_H2);
    }
}

// PV for ncc c-tiles (cc0..cc0+ncc-1) of key-group t2
DEVI void pv_piece(int t2, int cc0, int ncc, const uint32_t Pf[2][4],
                   uint32_t stX, int brow, int bhi, int xl, float O[2][16][4]) {
    const uint32_t cswB = (uint32_t)(((t2 * 2 + bhi) ^ xl) << 4);
    const uint32_t xrow = stX + (uint32_t)brow * 128;
#pragma unroll
    for (int c = 0; c < ncc; c++) {
        const int cc = cc0 + c;
        uint32_t xb[4];
        ldsm4(xb, xrow + cc * 16 * 128 + cswB);
        mma16816(O[0][2 * cc],     Pf[0], xb[0], xb[1]);
        mma16816(O[0][2 * cc + 1], Pf[0], xb[2], xb[3]);
        mma16816(O[1][2 * cc],     Pf[1], xb[0], xb[1]);
        mma16816(O[1][2 * cc + 1], Pf[1], xb[2], xb[3]);
    }
}

DEVI void zero_S(float S[2][4][4]) {
#pragma unroll
    for (int t = 0; t < 2; t++)
#pragma unroll
        for (int i = 0; i < 4; i++) { S[t][i][0] = S[t][i][1] = S[t][i][2] = S[t][i][3] = 0.f; }
}

// plain QK of one half (prologue)
DEVI void qk_half(float S[2][4][4], uint32_t stK, int h,
                  uint32_t qrow0, uint32_t qrow1, int brow, int ahi, int bhi, int xl) {
#pragma unroll
    for (int kt = 0; kt < 16; kt++)
        qk_step(kt, S, stK, h, qrow0, qrow1, brow, ahi, bhi, xl);
}

// plain exp+PV of one half (tail)
DEVI void exppv_half(const float S[2][4][4], uint32_t stX, int h,
                     float O[2][16][4], float den[2][4], int brow, int bhi, int xl) {
#pragma unroll
    for (int g = 0; g < 2; g++) {
        uint32_t Pf[2][4];
        exp_piece(g, S, Pf, den);
        pv_piece(2 * h + g, 0, 8, Pf, stX, brow, bhi, xl, O);
    }
}

// pipelined block: QK(Snew; stK_new, h_new) interleaved with exp+PV(Sold; h_old)
DEVI void fused_block(float Snew[2][4][4], uint32_t stK_new, int h_new,
                      const float Sold[2][4][4], uint32_t stX_old, int h_old,
                      float O[2][16][4], float den[2][4],
                      uint32_t qrow0, uint32_t qrow1, int brow, int ahi, int bhi, int xl) {
    uint32_t Pf0[2][4], Pf1[2][4];
#pragma unroll
    for (int kt = 0; kt < 16; kt++) {
        qk_step(kt, Snew, stK_new, h_new, qrow0, qrow1, brow, ahi, bhi, xl);
        if (kt == 2)  exp_piece(0, Sold, Pf0, den);
        if (kt >= 4 && kt < 8)
            pv_piece(2 * h_old + 0, (kt - 4) * 2, 2, Pf0, stX_old, brow, bhi, xl, O);
        if (kt == 9)  exp_piece(1, Sold, Pf1, den);
        if (kt >= 11 && kt < 15)
            pv_piece(2 * h_old + 1, (kt - 11) * 2, 2, Pf1, stX_old, brow, bhi, xl, O);
    }
}

// ---------------- main fused attention kernel -------------------------------
__global__ void __launch_bounds__(256, 1) attn_kernel(float* __restrict__ out) {
    extern __shared__ __align__(1024) char smem[];
    const uint32_t sb = smem_u32(smem);
    const int tid = threadIdx.x;
    const int wid = tid >> 5;
    const int lane = tid & 31;
    const int b = blockIdx.y;
    const int k0 = blockIdx.x * MT;
    const int qb = wid * 32;             // this warp's 32 query rows (2 m-tiles)

    // ---- issue Q (group0), chunk0 (group1), chunk1 (group2) ----
    {
        const __half* qbase = g_Qf + ((size_t)(b * N_ + k0)) * F_;
#pragma unroll
        for (int i = 0; i < 32; i++) {
            int lin = tid + i * 256;      // 0..8191
            int row = lin >> 5;           // 0..255
            int ch  = lin & 31;
            cp_async16(sb + SM_Q + row * 512 + ((ch ^ (row & 7)) << 4),
                       qbase + (size_t)row * F_ + ch * 8);
        }
        cp_commit();
    }
    load_chunk(b, 0, 0, sb, tid);
    load_chunk(b, KT, 1, sb, tid);

    float O[2][16][4];
#pragma unroll
    for (int t = 0; t < 2; t++)
#pragma unroll
        for (int i = 0; i < 16; i++) { O[t][i][0] = O[t][i][1] = O[t][i][2] = O[t][i][3] = 0.f; }
    float den_acc[2][4];
#pragma unroll
    for (int t = 0; t < 2; t++) { den_acc[t][0] = den_acc[t][1] = den_acc[t][2] = den_acc[t][3] = 0.f; }

    // ldmatrix lane maps (verified R7+).
    const int arow = lane & 15;
    const int ahi  = lane >> 4;
    const int brow = (lane & 7) + ((lane >> 4) << 3);
    const int bhi  = (lane >> 3) & 1;
    const int xl   = lane & 7;
    const uint32_t qrow0 = sb + SM_Q + (qb + arow) * 512;
    const uint32_t qrow1 = qrow0 + 16 * 512;

    // ---- prologue: wait Q + chunk0, compute S_cur = QK(chunk0, half0) ----
    cp_wait1();
    __syncthreads();
    float Scur[2][4][4], Snext[2][4][4];
    zero_S(Scur);
    qk_half(Scur, sb + SM_K, 0, qrow0, qrow1, brow, ahi, bhi, xl);

    for (int j = 0; j < NCHUNK; j++) {
        const uint32_t stKj = sb + SM_K + (j & 1) * KSTAGE;
        const uint32_t stXj = sb + SM_X + (j & 1) * XSTAGE;

        // step A: QK(j, h1) || exp+PV(j, h0)
        zero_S(Snext);
        fused_block(Snext, stKj, 1, Scur, stXj, 0, O, den_acc,
                    qrow0, qrow1, brow, ahi, bhi, xl);

        if (j + 1 < NCHUNK) {
            cp_wait0();                   // chunk j+1 resident
            __syncthreads();
            const uint32_t stKn = sb + SM_K + ((j + 1) & 1) * KSTAGE;
            // step B: QK(j+1, h0) || exp+PV(j, h1)
            zero_S(Scur);
            fused_block(Scur, stKn, 0, Snext, stXj, 1, O, den_acc,
                        qrow0, qrow1, brow, ahi, bhi, xl);
            __syncthreads();              // stage j&1 fully consumed
            if (j + 2 < NCHUNK) load_chunk(b, (j + 2) * KT, j & 1, sb, tid);
        } else {
            // tail: exp+PV(j, h1)
            exppv_half(Snext, stXj, 1, O, den_acc, brow, bhi, xl);
        }
    }

    // ---- epilogue: scale by 1/den (den replicated across quad lanes) ----
#pragma unroll
    for (int t = 0; t < 2; t++) {
        float inv0 = 1.0f / den_acc[t][0];   // row g
        float inv1 = 1.0f / den_acc[t][2];   // row g+8

        int r0 = k0 + qb + t * 16 + (lane >> 2);
        int r1 = r0 + 8;
        float* o0 = out + ((size_t)(b * N_ + r0)) * D_ + (lane & 3) * 2;
        float* o1 = out + ((size_t)(b * N_ + r1)) * D_ + (lane & 3) * 2;
#pragma unroll
        for (int nt = 0; nt < 16; nt++) {
            *(float2*)(o0 + nt * 8) = make_float2(O[t][nt][0] * inv0, O[t][nt][1] * inv0);
            *(float2*)(o1 + nt * 8) = make_float2(O[t][nt][2] * inv1, O[t][nt][3] * inv1);
        }
    }
}

// ---------------- launch ----------------------------------------------------
extern "C" void kernel_launch(void* const* d_in, const int* in_sizes, int n_in,
                              void* d_out, int out_size) {
    const float* x  = (const float*)d_in[0];
    const float* e  = (const float*)d_in[1];
    const float* d  = (const float*)d_in[2];
    const float* W1 = (const float*)d_in[3];
    const float* W2 = (const float*)d_in[4];
    float* out = (float*)d_out;

    cudaFuncSetAttribute(attn_kernel, cudaFuncAttributeMaxDynamicSharedMemorySize, SMEM_TOTAL);

    int threads = 256;
    int blocks = (int)(((size_t)B_ * N_ * (F_ / 4) + threads - 1) / threads);
    build_qk<<<blocks, threads>>>(e, d, W1, W2);

    dim3 tg(N_ / 32, D_ / 32, B_);
    transpose_x<<<tg, dim3(32, 8)>>>(x);

    attn_kernel<<<dim3(N_ / MT, B_), 256, SMEM_TOTAL>>>(out);
}

// round 12
// speedup vs baseline: 1.1132x; 1.1132x over previous
#include <cuda_runtime.h>
#include <cuda_fp16.h>
#include <cstdint>

// ============================================================
// out[b,k,c] = softmax_m( tanh(e[b,m]·W1[k] + d[b,k]·W2[m]) ) · x[b,m,c]
// B=16, N=2048, D=128.
// Flash-style fused attention, mma.sync.m16n8k16 + ldmatrix + cp.async.
// tanh bounds scores in [-1,1] -> no online max rescaling needed.
// R11: revert R10 pipeline (regressed: spills). Base = R8 (178.1us).
//      (a) drop transpose_x: PV uses ldmatrix.x4.trans on row-major Xh,
//      (b) single fully-coalesced prep kernel (warp-per-row-half),
//      (c) 2 launches instead of 3.
// ============================================================

#define DEVI __device__ __forceinline__

constexpr int B_ = 16, N_ = 2048, D_ = 128, F_ = 256;
constexpr int MT = 256;              // queries per CTA
constexpr int KT = 64;               // keys per chunk
constexpr int NCHUNK = N_ / KT;      // 32

// ---------------- device scratch -------------------------------------------
__device__ __half g_Qf[(size_t)B_ * N_ * F_];   // [b,k,256] = [W1[k] | d[b,k]]
__device__ __half g_Kf[(size_t)B_ * N_ * F_];   // [b,m,256] = [e[b,m] | W2[m]]
__device__ __half g_Xh[(size_t)B_ * N_ * D_];   // [b,m,c]   = fp16(x[b,m,c])

// ---------------- SMEM layout (bytes), XOR-swizzled, no padding -------------
// Q/K rows: 512B (32 x 16B chunks); X rows: 256B (16 x 16B chunks).
// phys_chunk = chunk ^ (row & 7) -> ldmatrix 8-row reads bank-conflict-free.
constexpr int SM_Q   = 0;
constexpr int QSIZE  = MT * 512;                // 131072
constexpr int KSTAGE = KT * 512;                // 32768
constexpr int SM_K   = SM_Q + QSIZE;
constexpr int XSTAGE = KT * 256;                // 16384 (64 m-rows x 256B)
constexpr int SM_X   = SM_K + 2 * KSTAGE;
constexpr int SMEM_TOTAL = SM_X + 2 * XSTAGE;   // 229376 (224 KB)

// ---------------- PTX helpers ----------------------------------------------
DEVI uint32_t smem_u32(const void* p) {
    uint32_t a;
    asm("{ .reg .u64 t; cvta.to.shared.u64 t, %1; cvt.u32.u64 %0, t; }" : "=r"(a) : "l"(p));
    return a;
}
DEVI float ex2f(float x) { float y; asm("ex2.approx.f32 %0,%1;" : "=f"(y) : "f"(x)); return y; }
DEVI float tanhf_hw(float x) { float y; asm("tanh.approx.f32 %0,%1;" : "=f"(y) : "f"(x)); return y; }

DEVI void cp_async16(uint32_t dst, const void* src) {
    asm volatile("cp.async.cg.shared.global [%0], [%1], 16;" :: "r"(dst), "l"(src) : "memory");
}
DEVI void cp_commit() { asm volatile("cp.async.commit_group;" ::: "memory"); }
DEVI void cp_wait0()  { asm volatile("cp.async.wait_group 0;" ::: "memory"); }
DEVI void cp_wait1()  { asm volatile("cp.async.wait_group 1;" ::: "memory"); }
DEVI void cp_wait2()  { asm volatile("cp.async.wait_group 2;" ::: "memory"); }

DEVI void ldsm4(uint32_t r[4], uint32_t addr) {
    asm volatile("ldmatrix.sync.aligned.m8n8.x4.shared.b16 {%0,%1,%2,%3}, [%4];"
                 : "=r"(r[0]), "=r"(r[1]), "=r"(r[2]), "=r"(r[3]) : "r"(addr));
}
DEVI void ldsm4t(uint32_t r[4], uint32_t addr) {
    asm volatile("ldmatrix.sync.aligned.m8n8.x4.trans.shared.b16 {%0,%1,%2,%3}, [%4];"
                 : "=r"(r[0]), "=r"(r[1]), "=r"(r[2]), "=r"(r[3]) : "r"(addr));
}
DEVI void mma16816(float d[4], const uint32_t a[4], uint32_t b0, uint32_t b1) {
    asm volatile("mma.sync.aligned.m16n8k16.row.col.f32.f16.f16.f32 "
                 "{%0,%1,%2,%3}, {%4,%5,%6,%7}, {%8,%9}, {%0,%1,%2,%3};"
                 : "+f"(d[0]), "+f"(d[1]), "+f"(d[2]), "+f"(d[3])
                 : "r"(a[0]), "r"(a[1]), "r"(a[2]), "r"(a[3]), "r"(b0), "r"(b1));
}

DEVI uint32_t h2_as_u32(__half2 h) { uint32_t u; __builtin_memcpy(&u, &h, 4); return u; }

// w = exp(tanh(s) - 1) = 2^( log2e*(tanh(s) - 1) )   (shift-invariant weight)
DEVI float wfun(float s) {
    const float l2e = 1.4426950409f;
    float t = tanhf_hw(s);
    return ex2f(fmaf(t, l2e, -l2e));
}

// ---------------- merged prep: Qf/Kf + Xh, warp-per-row-half ----------------
// warps [0, B*N*2):  h = w&1, k = (w>>1)&2047, b = w>>12
//   h=0: Qf[b,k,0:128]  = fp16(W1[k]),  Kf[b,k,0:128]  = fp16(e[b,k])
//   h=1: Qf[b,k,128:256]= fp16(d[b,k]), Kf[b,k,128:256]= fp16(W2[k])
// warps [B*N*2, B*N*3): m = w2&2047, b = w2>>11 : Xh[b,m,:] = fp16(x[b,m,:])
constexpr int QK_WARPS = B_ * N_ * 2;           // 65536
constexpr int PREP_WARPS = QK_WARPS + B_ * N_;  // 98304

__global__ void prep_all(const float* __restrict__ e, const float* __restrict__ d,
                         const float* __restrict__ W1, const float* __restrict__ W2,
                         const float* __restrict__ x) {
    int w    = (int)((blockIdx.x * blockDim.x + threadIdx.x) >> 5);
    int lane = threadIdx.x & 31;
    if (w < QK_WARPS) {
        int h = w & 1;
        int k = (w >> 1) & (N_ - 1);
        int b = w >> 12;
        const float4* qsrc;
        const float4* ksrc;
        if (h == 0) {
            qsrc = (const float4*)(W1 + (size_t)k * D_);
            ksrc = (const float4*)(e + ((size_t)(b * N_ + k)) * D_);
        } else {
            qsrc = (const float4*)(d + ((size_t)(b * N_ + k)) * D_);
            ksrc = (const float4*)(W2 + (size_t)k * D_);
        }
        float4 qv = qsrc[lane];
        float4 kv = ksrc[lane];
        uint2 qo = make_uint2(h2_as_u32(__floats2half2_rn(qv.x, qv.y)),
                              h2_as_u32(__floats2half2_rn(qv.z, qv.w)));
        uint2 ko = make_uint2(h2_as_u32(__floats2half2_rn(kv.x, kv.y)),
                              h2_as_u32(__floats2half2_rn(kv.z, kv.w)));
        size_t roff = ((size_t)(b * N_ + k)) * F_ + h * 128 + lane * 4;
        *(uint2*)(g_Qf + roff) = qo;
        *(uint2*)(g_Kf + roff) = ko;
    } else if (w < PREP_WARPS) {
        int w2 = w - QK_WARPS;
        int m = w2 & (N_ - 1);
        int b = w2 >> 11;
        float4 v = ((const float4*)(x + ((size_t)(b * N_ + m)) * D_))[lane];
        uint2 o = make_uint2(h2_as_u32(__floats2half2_rn(v.x, v.y)),
                             h2_as_u32(__floats2half2_rn(v.z, v.w)));
        *(uint2*)(g_Xh + ((size_t)(b * N_ + m)) * D_ + lane * 4) = o;
    }
}

// ---------------- chunk loader: K (64x256) + Xh (64x128), swizzled ----------
DEVI void load_chunk(int b, int m0, int stage, uint32_t sb, int tid) {
    const uint32_t stK = sb + SM_K + stage * KSTAGE;
    const uint32_t stX = sb + SM_X + stage * XSTAGE;
    const __half* kbase = g_Kf + ((size_t)(b * N_ + m0)) * F_;
#pragma unroll
    for (int i = 0; i < 8; i++) {
        int lin = tid + i * 256;          // 0..2047
        int row = lin >> 5;               // 0..63
        int ch  = lin & 31;
        cp_async16(stK + row * 512 + ((ch ^ (row & 7)) << 4),
                   kbase + (size_t)row * F_ + ch * 8);
    }
    const __half* xbase = g_Xh + ((size_t)(b * N_ + m0)) * D_;
#pragma unroll
    for (int i = 0; i < 4; i++) {
        int lin = tid + i * 256;          // 0..1023
        int row = lin >> 4;               // m: 0..63
        int ch  = lin & 15;               // 16B chunk within 256B row
        cp_async16(stX + row * 256 + ((ch ^ (row & 7)) << 4),
                   xbase + (size_t)row * D_ + ch * 8);
    }
    cp_commit();
}

// ---------------- main fused attention kernel -------------------------------
__global__ void __launch_bounds__(256, 1) attn_kernel(float* __restrict__ out) {
    extern __shared__ __align__(1024) char smem[];
    const uint32_t sb = smem_u32(smem);
    const int tid = threadIdx.x;
    const int wid = tid >> 5;
    const int lane = tid & 31;
    const int b = blockIdx.y;
    const int k0 = blockIdx.x * MT;
    const int qb = wid * 32;             // this warp's 32 query rows (2 m-tiles)

    // ---- issue Q (group0), chunk0 (group1), chunk1 (group2) ----
    {
        const __half* qbase = g_Qf + ((size_t)(b * N_ + k0)) * F_;
#pragma unroll
        for (int i = 0; i < 32; i++) {
            int lin = tid + i * 256;      // 0..8191
            int row = lin >> 5;           // 0..255
            int ch  = lin & 31;
            cp_async16(sb + SM_Q + row * 512 + ((ch ^ (row & 7)) << 4),
                       qbase + (size_t)row * F_ + ch * 8);
        }
        cp_commit();
    }
    load_chunk(b, 0, 0, sb, tid);
    load_chunk(b, KT, 1, sb, tid);

    float O[2][16][4];
#pragma unroll
    for (int t = 0; t < 2; t++)
#pragma unroll
        for (int i = 0; i < 16; i++) { O[t][i][0] = O[t][i][1] = O[t][i][2] = O[t][i][3] = 0.f; }
    float den[2][2] = {{0.f, 0.f}, {0.f, 0.f}};

    // ldmatrix lane maps (verified R7+).
    // A (Q) and trans-X: row = lane&15, chunk-half = lane>>4.
    // B (K) non-trans:   row = (lane&7)+((lane>>4)<<3), chunk-half = (lane>>3)&1.
    const int arow = lane & 15;
    const int ahi  = lane >> 4;
    const int brow = (lane & 7) + ((lane >> 4) << 3);
    const int bhi  = (lane >> 3) & 1;
    const int xl   = lane & 7;           // row&7 for ALL maps (tile bases %16==0)
    const uint32_t qrow0 = sb + SM_Q + (qb + arow) * 512;
    const uint32_t qrow1 = qrow0 + 16 * 512;

    cp_wait2();                           // Q group complete
    __syncthreads();

    for (int j = 0; j < NCHUNK; j++) {
        if (j + 1 < NCHUNK) cp_wait1(); else cp_wait0();
        __syncthreads();
        const uint32_t stK = sb + SM_K + (j & 1) * KSTAGE;
        const uint32_t stX = sb + SM_X + (j & 1) * XSTAGE;
        const uint32_t krow = stK + brow * 512;
        const uint32_t xrowA = stX + arow * 256;   // trans-X: rows are m

        // ---- QK: S[32 x 64] = Q @ Kchunk^T (2 m-tiles share every K frag) ----
        float S[2][8][4];
#pragma unroll
        for (int t = 0; t < 2; t++)
#pragma unroll
            for (int i = 0; i < 8; i++) { S[t][i][0] = S[t][i][1] = S[t][i][2] = S[t][i][3] = 0.f; }

#pragma unroll
        for (int kt = 0; kt < 16; kt++) {
            const uint32_t cswA = (uint32_t)(((kt * 2 + ahi) ^ xl) << 4);
            const uint32_t cswB = (uint32_t)(((kt * 2 + bhi) ^ xl) << 4);
            uint32_t qa0[4], qa1[4];
            ldsm4(qa0, qrow0 + cswA);
            ldsm4(qa1, qrow1 + cswA);
#pragma unroll
            for (int ng = 0; ng < 4; ng++) {
                uint32_t kb[4];
                ldsm4(kb, krow + ng * 16 * 512 + cswB);
                mma16816(S[0][2 * ng],     qa0, kb[0], kb[1]);
                mma16816(S[0][2 * ng + 1], qa0, kb[2], kb[3]);
                mma16816(S[1][2 * ng],     qa1, kb[0], kb[1]);
                mma16816(S[1][2 * ng + 1], qa1, kb[2], kb[3]);
            }
        }

        // ---- per t2-group: weights -> pack -> PV (trans-ldsm X) ----
#pragma unroll
        for (int t2 = 0; t2 < 4; t2++) {
            uint32_t Pf[2][4];
#pragma unroll
            for (int t = 0; t < 2; t++) {
                int j0 = 2 * t2, j1 = 2 * t2 + 1;
                __half2 h00 = __floats2half2_rn(wfun(S[t][j0][0]), wfun(S[t][j0][1]));
                __half2 h01 = __floats2half2_rn(wfun(S[t][j0][2]), wfun(S[t][j0][3]));
                __half2 h10 = __floats2half2_rn(wfun(S[t][j1][0]), wfun(S[t][j1][1]));
                __half2 h11 = __floats2half2_rn(wfun(S[t][j1][2]), wfun(S[t][j1][3]));
                float2 f;
                f = __half22float2(h00); den[t][0] += f.x + f.y;
                f = __half22float2(h01); den[t][1] += f.x + f.y;
                f = __half22float2(h10); den[t][0] += f.x + f.y;
                f = __half22float2(h11); den[t][1] += f.x + f.y;
                Pf[t][0] = h2_as_u32(h00);   // a0: row g,   k 0-7  of this 16-key tile
                Pf[t][1] = h2_as_u32(h01);   // a1: row g+8, k 0-7
                Pf[t][2] = h2_as_u32(h10);   // a2: row g,   k 8-15
                Pf[t][3] = h2_as_u32(h11);   // a3: row g+8, k 8-15
            }
            // PV: X tile rows m = t2*16 + arow, c-chunk = cc*2 + ahi (trans)
            const uint32_t xb_base = xrowA + t2 * 16 * 256;
#pragma unroll
            for (int cc = 0; cc < 8; cc++) {
                uint32_t xb[4];
                ldsm4t(xb, xb_base + (uint32_t)((((cc * 2 + ahi) ^ xl)) << 4));
                mma16816(O[0][2 * cc],     Pf[0], xb[0], xb[1]);
                mma16816(O[0][2 * cc + 1], Pf[0], xb[2], xb[3]);
                mma16816(O[1][2 * cc],     Pf[1], xb[0], xb[1]);
                mma16816(O[1][2 * cc + 1], Pf[1], xb[2], xb[3]);
            }
        }

        __syncthreads();                  // all warps done with stage (j&1)
        if (j + 2 < NCHUNK) load_chunk(b, (j + 2) * KT, j & 1, sb, tid);
    }

    // ---- epilogue: quad-reduce denom, scale, store ----
#pragma unroll
    for (int t = 0; t < 2; t++) {
        float d0 = den[t][0], d1 = den[t][1];
        d0 += __shfl_xor_sync(0xffffffffu, d0, 1);
        d0 += __shfl_xor_sync(0xffffffffu, d0, 2);
        d1 += __shfl_xor_sync(0xffffffffu, d1, 1);
        d1 += __shfl_xor_sync(0xffffffffu, d1, 2);
        float inv0 = 1.0f / d0, inv1 = 1.0f / d1;

        int r0 = k0 + qb + t * 16 + (lane >> 2);
        int r1 = r0 + 8;
        float* o0 = out + ((size_t)(b * N_ + r0)) * D_ + (lane & 3) * 2;
        float* o1 = out + ((size_t)(b * N_ + r1)) * D_ + (lane & 3) * 2;
#pragma unroll
        for (int nt = 0; nt < 16; nt++) {
            *(float2*)(o0 + nt * 8) = make_float2(O[t][nt][0] * inv0, O[t][nt][1] * inv0);
            *(float2*)(o1 + nt * 8) = make_float2(O[t][nt][2] * inv1, O[t][nt][3] * inv1);
        }
    }
}

// ---------------- launch ----------------------------------------------------
extern "C" void kernel_launch(void* const* d_in, const int* in_sizes, int n_in,
                              void* d_out, int out_size) {
    const float* x  = (const float*)d_in[0];
    const float* e  = (const float*)d_in[1];
    const float* d  = (const float*)d_in[2];
    const float* W1 = (const float*)d_in[3];
    const float* W2 = (const float*)d_in[4];
    float* out = (float*)d_out;

    cudaFuncSetAttribute(attn_kernel, cudaFuncAttributeMaxDynamicSharedMemorySize, SMEM_TOTAL);

    // one merged prep kernel: 98304 warps, 8 warps per 256-thread block
    prep_all<<<PREP_WARPS / 8, 256>>>(e, d, W1, W2, x);

    attn_kernel<<<dim3(N_ / MT, B_), 256, SMEM_TOTAL>>>(out);
}

// round 13
// speedup vs baseline: 1.1252x; 1.0108x over previous
#include <cuda_runtime.h>
#include <cuda_fp16.h>
#include <cstdint>

// ============================================================
// out[b,k,c] = softmax_m( tanh(e[b,m]·W1[k] + d[b,k]·W2[m]) ) · x[b,m,c]
// B=16, N=2048, D=128.
// Flash-style fused attention, mma.sync.m16n8k16 + ldmatrix + cp.async.
// tanh bounds scores in [-1,1] -> no online max rescaling needed.
// R12: best-of-both recombination:
//   - attn_kernel = exact R8 (non-trans X ldmatrix; trans was ~20us slower)
//   - prep = R11's warp-coalesced merged Qf/Kf kernel (~3us) + transpose_x
// ============================================================

#define DEVI __device__ __forceinline__

constexpr int B_ = 16, N_ = 2048, D_ = 128, F_ = 256;
constexpr int MT = 256;              // queries per CTA
constexpr int KT = 64;               // keys per chunk
constexpr int NCHUNK = N_ / KT;      // 32

// ---------------- device scratch -------------------------------------------
__device__ __half g_Qf[(size_t)B_ * N_ * F_];   // [b,k,256] = [W1[k] | d[b,k]]
__device__ __half g_Kf[(size_t)B_ * N_ * F_];   // [b,m,256] = [e[b,m] | W2[m]]
__device__ __half g_XT[(size_t)B_ * D_ * N_];   // [b,c,m]   = x[b,m,c]

// ---------------- SMEM layout (bytes), XOR-swizzled, no padding -------------
// Q/K rows: 512B (32 x 16B chunks), X rows: 128B (8 x 16B chunks).
// phys_chunk = chunk ^ (row & 7)  -> ldmatrix 8-row reads are bank-conflict-free.
constexpr int SM_Q   = 0;
constexpr int QSIZE  = MT * 512;                // 131072
constexpr int KSTAGE = KT * 512;                // 32768
constexpr int SM_K   = SM_Q + QSIZE;
constexpr int XSTAGE = D_ * 128;                // 16384
constexpr int SM_X   = SM_K + 2 * KSTAGE;
constexpr int SMEM_TOTAL = SM_X + 2 * XSTAGE;   // 229376 (224 KB)

// ---------------- PTX helpers ----------------------------------------------
DEVI uint32_t smem_u32(const void* p) {
    uint32_t a;
    asm("{ .reg .u64 t; cvta.to.shared.u64 t, %1; cvt.u32.u64 %0, t; }" : "=r"(a) : "l"(p));
    return a;
}
DEVI float ex2f(float x) { float y; asm("ex2.approx.f32 %0,%1;" : "=f"(y) : "f"(x)); return y; }
DEVI float tanhf_hw(float x) { float y; asm("tanh.approx.f32 %0,%1;" : "=f"(y) : "f"(x)); return y; }

DEVI void cp_async16(uint32_t dst, const void* src) {
    asm volatile("cp.async.cg.shared.global [%0], [%1], 16;" :: "r"(dst), "l"(src) : "memory");
}
DEVI void cp_commit() { asm volatile("cp.async.commit_group;" ::: "memory"); }
DEVI void cp_wait0()  { asm volatile("cp.async.wait_group 0;" ::: "memory"); }
DEVI void cp_wait1()  { asm volatile("cp.async.wait_group 1;" ::: "memory"); }
DEVI void cp_wait2()  { asm volatile("cp.async.wait_group 2;" ::: "memory"); }

DEVI void ldsm4(uint32_t r[4], uint32_t addr) {
    asm volatile("ldmatrix.sync.aligned.m8n8.x4.shared.b16 {%0,%1,%2,%3}, [%4];"
                 : "=r"(r[0]), "=r"(r[1]), "=r"(r[2]), "=r"(r[3]) : "r"(addr));
}
DEVI void mma16816(float d[4], const uint32_t a[4], uint32_t b0, uint32_t b1) {
    asm volatile("mma.sync.aligned.m16n8k16.row.col.f32.f16.f16.f32 "
                 "{%0,%1,%2,%3}, {%4,%5,%6,%7}, {%8,%9}, {%0,%1,%2,%3};"
                 : "+f"(d[0]), "+f"(d[1]), "+f"(d[2]), "+f"(d[3])
                 : "r"(a[0]), "r"(a[1]), "r"(a[2]), "r"(a[3]), "r"(b0), "r"(b1));
}

DEVI uint32_t h2_as_u32(__half2 h) { uint32_t u; __builtin_memcpy(&u, &h, 4); return u; }

// w = exp(tanh(s) - 1) = 2^( log2e*(tanh(s) - 1) )   (shift-invariant weight)
DEVI float wfun(float s) {
    const float l2e = 1.4426950409f;
    float t = tanhf_hw(s);
    return ex2f(fmaf(t, l2e, -l2e));
}

// ---------------- merged prep: Qf/Kf, warp-per-row-half (coalesced) ---------
// warps [0, B*N*2):  h = w&1, k = (w>>1)&2047, b = w>>12
//   h=0: Qf[b,k,0:128]  = fp16(W1[k]),  Kf[b,k,0:128]  = fp16(e[b,k])
//   h=1: Qf[b,k,128:256]= fp16(d[b,k]), Kf[b,k,128:256]= fp16(W2[k])
constexpr int QK_WARPS = B_ * N_ * 2;           // 65536

__global__ void prep_qk(const float* __restrict__ e, const float* __restrict__ d,
                        const float* __restrict__ W1, const float* __restrict__ W2) {
    int w    = (int)((blockIdx.x * blockDim.x + threadIdx.x) >> 5);
    int lane = threadIdx.x & 31;
    if (w >= QK_WARPS) return;
    int h = w & 1;
    int k = (w >> 1) & (N_ - 1);
    int b = w >> 12;
    const float4* qsrc;
    const float4* ksrc;
    if (h == 0) {
        qsrc = (const float4*)(W1 + (size_t)k * D_);
        ksrc = (const float4*)(e + ((size_t)(b * N_ + k)) * D_);
    } else {
        qsrc = (const float4*)(d + ((size_t)(b * N_ + k)) * D_);
        ksrc = (const float4*)(W2 + (size_t)k * D_);
    }
    float4 qv = qsrc[lane];
    float4 kv = ksrc[lane];
    uint2 qo = make_uint2(h2_as_u32(__floats2half2_rn(qv.x, qv.y)),
                          h2_as_u32(__floats2half2_rn(qv.z, qv.w)));
    uint2 ko = make_uint2(h2_as_u32(__floats2half2_rn(kv.x, kv.y)),
                          h2_as_u32(__floats2half2_rn(kv.z, kv.w)));
    size_t roff = ((size_t)(b * N_ + k)) * F_ + h * 128 + lane * 4;
    *(uint2*)(g_Qf + roff) = qo;
    *(uint2*)(g_Kf + roff) = ko;
}

// ---------------- prep: XT[b,c,m] = fp16(x[b,m,c]) --------------------------
__global__ void transpose_x(const float* __restrict__ x) {
    __shared__ float tile[32][33];
    int b = blockIdx.z;
    int m0 = blockIdx.x * 32, c0 = blockIdx.y * 32;
    int tx = threadIdx.x, ty = threadIdx.y;
#pragma unroll
    for (int i = 0; i < 4; i++)
        tile[ty + 8 * i][tx] = x[((size_t)(b * N_ + m0 + ty + 8 * i)) * D_ + c0 + tx];
    __syncthreads();
#pragma unroll
    for (int i = 0; i < 4; i++)
        g_XT[((size_t)(b * D_ + c0 + ty + 8 * i)) * N_ + m0 + tx] =
            __float2half_rn(tile[tx][ty + 8 * i]);
}

// ---------------- chunk loader: K (64x256) + XT (128x64), swizzled ----------
DEVI void load_chunk(int b, int m0, int stage, uint32_t sb, int tid) {
    const uint32_t stK = sb + SM_K + stage * KSTAGE;
    const uint32_t stX = sb + SM_X + stage * XSTAGE;
    const __half* kbase = g_Kf + ((size_t)(b * N_ + m0)) * F_;
#pragma unroll
    for (int i = 0; i < 8; i++) {
        int lin = tid + i * 256;          // 0..2047
        int row = lin >> 5;               // 0..63
        int ch  = lin & 31;
        cp_async16(stK + row * 512 + ((ch ^ (row & 7)) << 4),
                   kbase + (size_t)row * F_ + ch * 8);
    }
    const __half* xbase = g_XT + (size_t)b * D_ * N_ + m0;
#pragma unroll
    for (int i = 0; i < 4; i++) {
        int lin = tid + i * 256;          // 0..1023
        int row = lin >> 3;               // c: 0..127
        int ch  = lin & 7;
        cp_async16(stX + row * 128 + ((ch ^ (row & 7)) << 4),
                   xbase + (size_t)row * N_ + ch * 8);
    }
    cp_commit();
}

// ---------------- main fused attention kernel (exact R8) --------------------
__global__ void __launch_bounds__(256, 1) attn_kernel(float* __restrict__ out) {
    extern __shared__ __align__(1024) char smem[];
    const uint32_t sb = smem_u32(smem);
    const int tid = threadIdx.x;
    const int wid = tid >> 5;
    const int lane = tid & 31;
    const int b = blockIdx.y;
    const int k0 = blockIdx.x * MT;
    const int qb = wid * 32;             // this warp's 32 query rows (2 m-tiles)

    // ---- issue Q (group0), chunk0 (group1), chunk1 (group2) ----
    {
        const __half* qbase = g_Qf + ((size_t)(b * N_ + k0)) * F_;
#pragma unroll
        for (int i = 0; i < 32; i++) {
            int lin = tid + i * 256;      // 0..8191
            int row = lin >> 5;           // 0..255
            int ch  = lin & 31;
            cp_async16(sb + SM_Q + row * 512 + ((ch ^ (row & 7)) << 4),
                       qbase + (size_t)row * F_ + ch * 8);
        }
        cp_commit();
    }
    load_chunk(b, 0, 0, sb, tid);
    load_chunk(b, KT, 1, sb, tid);

    float O[2][16][4];
#pragma unroll
    for (int t = 0; t < 2; t++)
#pragma unroll
        for (int i = 0; i < 16; i++) { O[t][i][0] = O[t][i][1] = O[t][i][2] = O[t][i][3] = 0.f; }
    float den[2][2] = {{0.f, 0.f}, {0.f, 0.f}};

    // ldmatrix lane maps (verified R7+).
    // A (Q): row = lane&15, col-half = lane>>4.
    // B (K/X): row = (lane&7)+((lane>>4)<<3), col-half = (lane>>3)&1.
    const int arow = lane & 15;
    const int ahi  = lane >> 4;
    const int brow = (lane & 7) + ((lane >> 4) << 3);
    const int bhi  = (lane >> 3) & 1;
    const int xl   = lane & 7;           // row&7 for BOTH maps (tile bases %16==0)
    const uint32_t qrow0 = sb + SM_Q + (qb + arow) * 512;
    const uint32_t qrow1 = qrow0 + 16 * 512;

    cp_wait2();                           // Q group complete
    __syncthreads();

    for (int j = 0; j < NCHUNK; j++) {
        if (j + 1 < NCHUNK) cp_wait1(); else cp_wait0();
        __syncthreads();
        const uint32_t stK = sb + SM_K + (j & 1) * KSTAGE;
        const uint32_t stX = sb + SM_X + (j & 1) * XSTAGE;
        const uint32_t krow = stK + brow * 512;
        const uint32_t xrow = stX + brow * 128;

        // ---- QK: S[32 x 64] = Q @ Kchunk^T (2 m-tiles share every K frag) ----
        float S[2][8][4];
#pragma unroll
        for (int t = 0; t < 2; t++)
#pragma unroll
            for (int i = 0; i < 8; i++) { S[t][i][0] = S[t][i][1] = S[t][i][2] = S[t][i][3] = 0.f; }

#pragma unroll
        for (int kt = 0; kt < 16; kt++) {
            const uint32_t cswA = (uint32_t)(((kt * 2 + ahi) ^ xl) << 4);
            const uint32_t cswB = (uint32_t)(((kt * 2 + bhi) ^ xl) << 4);
            uint32_t qa0[4], qa1[4];
            ldsm4(qa0, qrow0 + cswA);
            ldsm4(qa1, qrow1 + cswA);
#pragma unroll
            for (int ng = 0; ng < 4; ng++) {
                uint32_t kb[4];
                ldsm4(kb, krow + ng * 16 * 512 + cswB);
                mma16816(S[0][2 * ng],     qa0, kb[0], kb[1]);
                mma16816(S[0][2 * ng + 1], qa0, kb[2], kb[3]);
                mma16816(S[1][2 * ng],     qa1, kb[0], kb[1]);
                mma16816(S[1][2 * ng + 1], qa1, kb[2], kb[3]);
            }
        }

        // ---- per t2-group: weights (tanh.approx + ex2) -> pack -> PV mma ----
#pragma unroll
        for (int t2 = 0; t2 < 4; t2++) {
            uint32_t Pf[2][4];
#pragma unroll
            for (int t = 0; t < 2; t++) {
                int j0 = 2 * t2, j1 = 2 * t2 + 1;
                __half2 h00 = __floats2half2_rn(wfun(S[t][j0][0]), wfun(S[t][j0][1]));
                __half2 h01 = __floats2half2_rn(wfun(S[t][j0][2]), wfun(S[t][j0][3]));
                __half2 h10 = __floats2half2_rn(wfun(S[t][j1][0]), wfun(S[t][j1][1]));
                __half2 h11 = __floats2half2_rn(wfun(S[t][j1][2]), wfun(S[t][j1][3]));
                float2 f;
                f = __half22float2(h00); den[t][0] += f.x + f.y;
                f = __half22float2(h01); den[t][1] += f.x + f.y;
                f = __half22float2(h10); den[t][0] += f.x + f.y;
                f = __half22float2(h11); den[t][1] += f.x + f.y;
                Pf[t][0] = h2_as_u32(h00);   // a0: row g,   k 0-7  of this 16-key tile
                Pf[t][1] = h2_as_u32(h01);   // a1: row g+8, k 0-7
                Pf[t][2] = h2_as_u32(h10);   // a2: row g,   k 8-15
                Pf[t][3] = h2_as_u32(h11);   // a3: row g+8, k 8-15
            }
            const uint32_t cswB = (uint32_t)(((t2 * 2 + bhi) ^ xl) << 4);
#pragma unroll
            for (int cc = 0; cc < 8; cc++) {
                uint32_t xb[4];
                ldsm4(xb, xrow + cc * 16 * 128 + cswB);
                mma16816(O[0][2 * cc],     Pf[0], xb[0], xb[1]);
                mma16816(O[0][2 * cc + 1], Pf[0], xb[2], xb[3]);
                mma16816(O[1][2 * cc],     Pf[1], xb[0], xb[1]);
                mma16816(O[1][2 * cc + 1], Pf[1], xb[2], xb[3]);
            }
        }

        __syncthreads();                  // all warps done with stage (j&1)
        if (j + 2 < NCHUNK) load_chunk(b, (j + 2) * KT, j & 1, sb, tid);
    }

    // ---- epilogue: quad-reduce denom, scale, store ----
#pragma unroll
    for (int t = 0; t < 2; t++) {
        float d0 = den[t][0], d1 = den[t][1];
        d0 += __shfl_xor_sync(0xffffffffu, d0, 1);
        d0 += __shfl_xor_sync(0xffffffffu, d0, 2);
        d1 += __shfl_xor_sync(0xffffffffu, d1, 1);
        d1 += __shfl_xor_sync(0xffffffffu, d1, 2);
        float inv0 = 1.0f / d0, inv1 = 1.0f / d1;

        int r0 = k0 + qb + t * 16 + (lane >> 2);
        int r1 = r0 + 8;
        float* o0 = out + ((size_t)(b * N_ + r0)) * D_ + (lane & 3) * 2;
        float* o1 = out + ((size_t)(b * N_ + r1)) * D_ + (lane & 3) * 2;
#pragma unroll
        for (int nt = 0; nt < 16; nt++) {
            *(float2*)(o0 + nt * 8) = make_float2(O[t][nt][0] * inv0, O[t][nt][1] * inv0);
            *(float2*)(o1 + nt * 8) = make_float2(O[t][nt][2] * inv1, O[t][nt][3] * inv1);
        }
    }
}

// ---------------- launch ----------------------------------------------------
extern "C" void kernel_launch(void* const* d_in, const int* in_sizes, int n_in,
                              void* d_out, int out_size) {
    const float* x  = (const float*)d_in[0];
    const float* e  = (const float*)d_in[1];
    const float* d  = (const float*)d_in[2];
    const float* W1 = (const float*)d_in[3];
    const float* W2 = (const float*)d_in[4];
    float* out = (float*)d_out;

    cudaFuncSetAttribute(attn_kernel, cudaFuncAttributeMaxDynamicSharedMemorySize, SMEM_TOTAL);

    // warp-coalesced Qf/Kf prep: 65536 warps, 8 warps per 256-thread block
    prep_qk<<<QK_WARPS / 8, 256>>>(e, d, W1, W2);

    dim3 tg(N_ / 32, D_ / 32, B_);
    transpose_x<<<tg, dim3(32, 8)>>>(x);

    attn_kernel<<<dim3(N_ / MT, B_), 256, SMEM_TOTAL>>>(out);
}